// round 5
// baseline (speedup 1.0000x reference)
#include <cuda_runtime.h>
#include <cuda_bf16.h>

// Enframe: out[b, w, f] = in[b, f*HOP + w],  b<16, w<2048, f<934, HOP=512.
// w = q*512 + r  =>  out[b, q*512+r, f] = in[b, (f+q)*512 + r]
// => 64 independent 512x934 fp32 transposes, 64x64 tiles.
//
// R4 (resubmit after infra failure): all stages 128-bit. Each thread loads a
// 4(r) x 4(f) block (4x LDG.128, consecutive f), transposes in registers,
// 4x STS.128 into an XOR-swizzled [64][64] tile (phys f-quad = fq ^ ((r>>2)&15)),
// then 4x LDS.128 + 8x STG.64 (output rows alternate 8B alignment -> no STG.128).

#define SAMPLES 480000
#define HOP     512
#define FRAMES  934          // even
#define OUT_W   2048
#define TF      64
#define TR      64

__global__ __launch_bounds__(256)
void enframe_transpose_kernel(const float* __restrict__ in,
                              float* __restrict__ out) {
    __shared__ float tile[TR][TF];      // [r][swizzled f-quads]

    const int bq = blockIdx.z;          // 0..63
    const int b  = bq >> 2;
    const int q  = bq & 3;
    const int f0 = blockIdx.x * TF;     // last tile partial (FRAMES=934)
    const int r0 = blockIdx.y * TR;

    const int tid = threadIdx.x;

    // ---- Load + register-transpose + STS.128 ----
    // thread: rv = (tid&15)*4 (r quad), fq = tid>>4 (f quad), c = rv>>2 = tid&15
    {
        const int c  = tid & 15;
        const int rv = c * 4;
        const int fq = tid >> 4;            // 0..15
        const int fb = f0 + 4 * fq;         // first f of this thread's quad
        const float* inb = in + (size_t)b * SAMPLES + r0 + rv;

        float4 v[4];
        if (f0 + TF <= FRAMES) {
            #pragma unroll
            for (int j = 0; j < 4; j++)
                v[j] = *(const float4*)(inb + (size_t)(fb + j + q) * HOP);
        } else {
            #pragma unroll
            for (int j = 0; j < 4; j++)
                v[j] = (fb + j < FRAMES)
                     ? *(const float4*)(inb + (size_t)(fb + j + q) * HOP)
                     : make_float4(0.f, 0.f, 0.f, 0.f);
        }

        const int pg = 4 * (fq ^ c);        // swizzled float offset in row
        *(float4*)&tile[rv + 0][pg] = make_float4(v[0].x, v[1].x, v[2].x, v[3].x);
        *(float4*)&tile[rv + 1][pg] = make_float4(v[0].y, v[1].y, v[2].y, v[3].y);
        *(float4*)&tile[rv + 2][pg] = make_float4(v[0].z, v[1].z, v[2].z, v[3].z);
        *(float4*)&tile[rv + 3][pg] = make_float4(v[0].w, v[1].w, v[2].w, v[3].w);
    }
    __syncthreads();

    // ---- LDS.128 + STG.64 ----
    // thread: g = tid&15 (f quad), rb = tid>>4, rows rb + 16i
    {
        const int g  = tid & 15;
        const int rb = tid >> 4;            // 0..15
        float* outb = out + ((size_t)b * OUT_W + (size_t)q * HOP) * FRAMES
                    + f0 + 4 * g;
        // FRAMES even => an even/odd f pair is valid iff its even f < FRAMES
        const bool ok0 = (f0 + 4 * g)     < FRAMES;
        const bool ok1 = (f0 + 4 * g + 2) < FRAMES;

        #pragma unroll
        for (int i = 0; i < 4; i++) {
            const int rl = rb + 16 * i;
            const int pg = 4 * (g ^ ((rl >> 2) & 15));
            float4 v = *(const float4*)&tile[rl][pg];
            float* p = outb + (size_t)(r0 + rl) * FRAMES;
            if (ok0) *(float2*)(p)     = make_float2(v.x, v.y);
            if (ok1) *(float2*)(p + 2) = make_float2(v.z, v.w);
        }
    }
}

extern "C" void kernel_launch(void* const* d_in, const int* in_sizes, int n_in,
                              void* d_out, int out_size) {
    const float* in = (const float*)d_in[0];
    float* out = (float*)d_out;

    dim3 block(256);
    dim3 grid((FRAMES + TF - 1) / TF,     // 15 f-tiles
              HOP / TR,                   // 8 r-tiles
              16 * 4);                    // (b, q)
    enframe_transpose_kernel<<<grid, block>>>(in, out);
}

// round 6
// speedup vs baseline: 1.1878x; 1.1878x over previous
#include <cuda_runtime.h>
#include <cuda_bf16.h>

// Enframe: out[b, w, f] = in[b, f*HOP + w],  b<16, w<2048, f<934, HOP=512.
// w = q*512 + r  =>  out[b, q*512+r, f] = in[b, (f+q)*512 + r]
// => 64 independent 512x934 fp32 transposes, 64x64 tiles.
//
// R6: R4 load side (4x LDG.128 batched, register 4x4 transpose, 4x STS.128,
// float4-granular XOR swizzle: phys quad = fq ^ ((r>>2)&15)) + R3 store side
// (warp per row-iteration, lane l -> f pair 2l: LDS.64 conflict-free,
// STG.64 fully packed 256B per warp).

#define SAMPLES 480000
#define HOP     512
#define FRAMES  934          // even
#define OUT_W   2048
#define TF      64
#define TR      64

__global__ __launch_bounds__(256)
void enframe_transpose_kernel(const float* __restrict__ in,
                              float* __restrict__ out) {
    __shared__ float tile[TR][TF];      // [r][swizzled f, float4-granular]

    const int bq = blockIdx.z;          // 0..63
    const int b  = bq >> 2;
    const int q  = bq & 3;
    const int f0 = blockIdx.x * TF;     // last tile partial (FRAMES=934)
    const int r0 = blockIdx.y * TR;

    const int tid = threadIdx.x;

    // ---- Load: 4x LDG.128 (4 consecutive f), register transpose, 4x STS.128
    {
        const int c  = tid & 15;            // r quad index
        const int rv = c * 4;
        const int fq = tid >> 4;            // f quad index, 0..15
        const int fb = f0 + 4 * fq;
        const float* inb = in + (size_t)b * SAMPLES + r0 + rv;

        float4 v[4];
        if (f0 + TF <= FRAMES) {
            #pragma unroll
            for (int j = 0; j < 4; j++)
                v[j] = *(const float4*)(inb + (size_t)(fb + j + q) * HOP);
        } else {
            #pragma unroll
            for (int j = 0; j < 4; j++)
                v[j] = (fb + j < FRAMES)
                     ? *(const float4*)(inb + (size_t)(fb + j + q) * HOP)
                     : make_float4(0.f, 0.f, 0.f, 0.f);
        }

        const int pg = 4 * (fq ^ c);        // swizzled float offset (16B aligned)
        *(float4*)&tile[rv + 0][pg] = make_float4(v[0].x, v[1].x, v[2].x, v[3].x);
        *(float4*)&tile[rv + 1][pg] = make_float4(v[0].y, v[1].y, v[2].y, v[3].y);
        *(float4*)&tile[rv + 2][pg] = make_float4(v[0].z, v[1].z, v[2].z, v[3].z);
        *(float4*)&tile[rv + 3][pg] = make_float4(v[0].w, v[1].w, v[2].w, v[3].w);
    }
    __syncthreads();

    // ---- Store: warp w handles rows w+8i; lane l -> f pair (2l, 2l+1)
    {
        const int l = tid & 31;
        const int w = tid >> 5;             // 0..7
        float* outb = out + ((size_t)b * OUT_W + (size_t)q * HOP) * FRAMES + f0;
        const bool ok = (f0 + 2 * l) < FRAMES;   // FRAMES even => pair valid

        #pragma unroll
        for (int i = 0; i < 8; i++) {
            const int rl = w + 8 * i;
            const int h  = (rl >> 2) & 15;
            // logical f pair l lives at float offset 4*((l>>1)^h) + 2*(l&1)
            const int off = 4 * ((l >> 1) ^ h) + 2 * (l & 1);
            if (ok) {
                float2 v = *(const float2*)&tile[rl][off];
                *(float2*)(outb + (size_t)(r0 + rl) * FRAMES + 2 * l) = v;
            }
        }
    }
}

extern "C" void kernel_launch(void* const* d_in, const int* in_sizes, int n_in,
                              void* d_out, int out_size) {
    const float* in = (const float*)d_in[0];
    float* out = (float*)d_out;

    dim3 block(256);
    dim3 grid((FRAMES + TF - 1) / TF,     // 15 f-tiles
              HOP / TR,                   // 8 r-tiles
              16 * 4);                    // (b, q)
    enframe_transpose_kernel<<<grid, block>>>(in, out);
}

// round 7
// speedup vs baseline: 1.2760x; 1.0742x over previous
#include <cuda_runtime.h>
#include <cuda_bf16.h>

// Enframe: out[b, w, f] = in[b, f*HOP + w],  b<16, w<2048, f<934, HOP=512.
// w = q*512 + r  =>  out[b, q*512+r, f] = in[b, (f+q)*512 + r]
// => 64 independent 512x934 fp32 transposes, 64x64 tiles.
//
// R7 = R6 body + __launch_bounds__(256, 8): force regs <= 32 so occupancy
// returns to ~90% (R6 measured regs=38 -> occ 67%, latency-bound with no
// unit saturated). Load: 4x LDG.128 batched (MLP), register 4x4 transpose,
// 4x STS.128 via float4-granular XOR swizzle (phys quad = fq ^ r_quad).
// Store: warp-per-row, lane l -> f pair 2l: conflict-free LDS.64 +
// fully-packed 256B/warp STG.64.

#define SAMPLES 480000
#define HOP     512
#define FRAMES  934          // even
#define OUT_W   2048
#define TF      64
#define TR      64

__global__ __launch_bounds__(256, 8)
void enframe_transpose_kernel(const float* __restrict__ in,
                              float* __restrict__ out) {
    __shared__ float tile[TR][TF];      // [r][swizzled f, float4-granular]

    const int bq = blockIdx.z;          // 0..63
    const int b  = bq >> 2;
    const int q  = bq & 3;
    const int f0 = blockIdx.x * TF;     // last tile partial (FRAMES=934)
    const int r0 = blockIdx.y * TR;

    const int tid = threadIdx.x;

    // ---- Load: 4x LDG.128 (4 consecutive f), register transpose, 4x STS.128
    {
        const int c  = tid & 15;            // r quad index
        const int rv = c * 4;
        const int fq = tid >> 4;            // f quad index, 0..15
        const int fb = f0 + 4 * fq;
        const float* inb = in + (size_t)b * SAMPLES + r0 + rv;

        float4 v[4];
        if (f0 + TF <= FRAMES) {
            #pragma unroll
            for (int j = 0; j < 4; j++)
                v[j] = *(const float4*)(inb + (size_t)(fb + j + q) * HOP);
        } else {
            #pragma unroll
            for (int j = 0; j < 4; j++)
                v[j] = (fb + j < FRAMES)
                     ? *(const float4*)(inb + (size_t)(fb + j + q) * HOP)
                     : make_float4(0.f, 0.f, 0.f, 0.f);
        }

        const int pg = 4 * (fq ^ c);        // swizzled float offset (16B aligned)
        *(float4*)&tile[rv + 0][pg] = make_float4(v[0].x, v[1].x, v[2].x, v[3].x);
        *(float4*)&tile[rv + 1][pg] = make_float4(v[0].y, v[1].y, v[2].y, v[3].y);
        *(float4*)&tile[rv + 2][pg] = make_float4(v[0].z, v[1].z, v[2].z, v[3].z);
        *(float4*)&tile[rv + 3][pg] = make_float4(v[0].w, v[1].w, v[2].w, v[3].w);
    }
    __syncthreads();

    // ---- Store: warp w handles rows w+8i; lane l -> f pair (2l, 2l+1)
    {
        const int l = tid & 31;
        const int w = tid >> 5;             // 0..7
        float* outb = out + ((size_t)b * OUT_W + (size_t)q * HOP) * FRAMES + f0;
        const bool ok = (f0 + 2 * l) < FRAMES;   // FRAMES even => pair valid

        #pragma unroll
        for (int i = 0; i < 8; i++) {
            const int rl = w + 8 * i;
            const int h  = (rl >> 2) & 15;
            // logical f pair l lives at float offset 4*((l>>1)^h) + 2*(l&1)
            const int off = 4 * ((l >> 1) ^ h) + 2 * (l & 1);
            if (ok) {
                float2 v = *(const float2*)&tile[rl][off];
                *(float2*)(outb + (size_t)(r0 + rl) * FRAMES + 2 * l) = v;
            }
        }
    }
}

extern "C" void kernel_launch(void* const* d_in, const int* in_sizes, int n_in,
                              void* d_out, int out_size) {
    const float* in = (const float*)d_in[0];
    float* out = (float*)d_out;

    dim3 block(256);
    dim3 grid((FRAMES + TF - 1) / TF,     // 15 f-tiles
              HOP / TR,                   // 8 r-tiles
              16 * 4);                    // (b, q)
    enframe_transpose_kernel<<<grid, block>>>(in, out);
}